// round 4
// baseline (speedup 1.0000x reference)
#include <cuda_runtime.h>
#include <cstdint>

#define NN   50000
#define TT   128
#define INF  6
#define HH   32
#define NE   2000
#define NI   150000
#define RRF  16

typedef unsigned long long u64;

// ---------------- scratch (device globals, no allocation) ----------------
__device__ float g_A  [NN * HH];
__device__ float g_XW [NN * HH];
__device__ float g_AGG[NN * HH];
__device__ float g_EF [NE * HH];
__device__ float g_degB[NE];
__device__ float g_degD[NN];
__device__ float g_XT [(size_t)TT * INF * NN];  // [t][f][node]

// ---------------- helpers ----------------
__device__ __forceinline__ u64 ffma2(u64 a, u64 b, u64 c) {
    u64 d;
    asm("fma.rn.f32x2 %0, %1, %2, %3;" : "=l"(d) : "l"(a), "l"(b), "l"(c));
    return d;
}
__device__ __forceinline__ u64 pk2(float lo, float hi) {
    u64 r;
    asm("mov.b64 %0, {%1, %2};" : "=l"(r) : "f"(lo), "f"(hi));
    return r;
}
__device__ __forceinline__ float2 up2(u64 v) {
    float2 f;
    asm("mov.b64 {%0, %1}, %2;" : "=f"(f.x), "=f"(f.y) : "l"(v));
    return f;
}
__device__ __forceinline__ float sigm(float x) {
    return __fdividef(1.f, 1.f + __expf(-x));
}
__device__ __forceinline__ float tanh_fast(float x) {
    return __fdividef(2.f, 1.f + __expf(-2.f * x)) - 1.f;
}

// ---------------- transpose price [n][t][f] -> [t][f][n] ----------------
// block: 64 nodes x 16 timesteps. Writes are 256B-contiguous runs in n.
__global__ void __launch_bounds__(256) transpose_kernel(const float* __restrict__ x) {
    __shared__ float s[64 * 97];            // 64 nodes x 96 (t,f) + pad
    const int n0 = blockIdx.x * 64;
    const int t0 = blockIdx.y * 16;         // timestep base of this tile
    for (int i = threadIdx.x; i < 64 * 96; i += 256) {
        int n = i / 96, j = i % 96;
        int nc = n0 + n < NN ? n0 + n : NN - 1;
        // tile covers elements [t0*INF, t0*INF + 96) of this node's row
        s[n * 97 + j] = x[(size_t)nc * (TT * INF) + t0 * INF + j];
    }
    __syncthreads();
    for (int i = threadIdx.x; i < 64 * 96; i += 256) {
        int row = i >> 6, n = i & 63;       // row = t_local*6 + f
        if (n0 + n < NN)
            g_XT[((size_t)t0 * INF + row) * NN + n0 + n] = s[n * 97 + row];
    }
}

// ---------------- GRU kernel ----------------
// 2 threads per node: lane = half*16 + nsub. Each thread computes 16 of the
// 32 outputs (8 f32x2 accumulators); halves exchange h via shfl.xor(16).
struct __align__(16) SmemGRU {
    u64 wn[32 * 16], wr[32 * 16], wz[32 * 16];  // W_hh pairs [k][jp]
    u64 uin[6 * 16], uir[6 * 16], uiz[6 * 16];  // W_ih pairs [f][jp]
    u64 bhn[16], br[16], bz[16], bin[16];
};

__global__ void __launch_bounds__(128, 5) gru_kernel(
    const float* __restrict__ W_ih, const float* __restrict__ W_hh,
    const float* __restrict__ b_ih, const float* __restrict__ b_hh)
{
    __shared__ SmemGRU sm;
    const int tid = threadIdx.x;

    for (int idx = tid; idx < 512; idx += 128) {
        int k = idx >> 4, jp = idx & 15;
        sm.wn[idx] = pk2(W_hh[(64 + 2 * jp) * HH + k], W_hh[(64 + 2 * jp + 1) * HH + k]);
        sm.wr[idx] = pk2(W_hh[(     2 * jp) * HH + k], W_hh[(     2 * jp + 1) * HH + k]);
        sm.wz[idx] = pk2(W_hh[(32 + 2 * jp) * HH + k], W_hh[(32 + 2 * jp + 1) * HH + k]);
    }
    for (int idx = tid; idx < 96; idx += 128) {
        int f = idx >> 4, jp = idx & 15;
        sm.uin[idx] = pk2(W_ih[(64 + 2 * jp) * INF + f], W_ih[(64 + 2 * jp + 1) * INF + f]);
        sm.uir[idx] = pk2(W_ih[(     2 * jp) * INF + f], W_ih[(     2 * jp + 1) * INF + f]);
        sm.uiz[idx] = pk2(W_ih[(32 + 2 * jp) * INF + f], W_ih[(32 + 2 * jp + 1) * INF + f]);
    }
    if (tid < 16) {
        int jp = tid;
        sm.br [jp] = pk2(b_ih[2 * jp] + b_hh[2 * jp],
                         b_ih[2 * jp + 1] + b_hh[2 * jp + 1]);
        sm.bz [jp] = pk2(b_ih[32 + 2 * jp] + b_hh[32 + 2 * jp],
                         b_ih[32 + 2 * jp + 1] + b_hh[32 + 2 * jp + 1]);
        sm.bhn[jp] = pk2(b_hh[64 + 2 * jp], b_hh[64 + 2 * jp + 1]);
        sm.bin[jp] = pk2(b_ih[64 + 2 * jp], b_ih[64 + 2 * jp + 1]);
    }
    __syncthreads();

    const int lane = tid & 31;
    const int warp = tid >> 5;
    const int half = lane >> 4;      // 0: outputs 0..15, 1: outputs 16..31
    const int nsub = lane & 15;
    const int node = blockIdx.x * 64 + warp * 16 + nsub;
    const int nc = node < NN ? node : NN - 1;
    const int jb = half * 8;         // pair offset into [16] rows

    float hf[32];                    // full h (both halves), for k-loop
#pragma unroll
    for (int i = 0; i < 32; i++) hf[i] = 0.f;

    float xv[6], xn[6];
#pragma unroll
    for (int f = 0; f < 6; f++) xv[f] = g_XT[(size_t)f * NN + nc];

    u64 accN[8], accR[8];
    float newh[16];

    for (int t = 0; t < TT; t++) {
        if (t < TT - 1) {
#pragma unroll
            for (int f = 0; f < 6; f++)
                xn[f] = g_XT[((size_t)(t + 1) * INF + f) * NN + nc];
        }

        // ---- merged pass: accN = bhn + Whh_n h ; accR = br + Whh_r h ----
#pragma unroll
        for (int jp = 0; jp < 8; jp++) {
            accN[jp] = sm.bhn[jb + jp];
            accR[jp] = sm.br [jb + jp];
        }
#pragma unroll 8
        for (int k = 0; k < 32; k++) {
            u64 hd = pk2(hf[k], hf[k]);
            const ulonglong2* pn = reinterpret_cast<const ulonglong2*>(&sm.wn[k * 16 + jb]);
            const ulonglong2* pr = reinterpret_cast<const ulonglong2*>(&sm.wr[k * 16 + jb]);
#pragma unroll
            for (int j2 = 0; j2 < 4; j2++) {
                ulonglong2 a = pn[j2];
                accN[2 * j2]     = ffma2(a.x, hd, accN[2 * j2]);
                accN[2 * j2 + 1] = ffma2(a.y, hd, accN[2 * j2 + 1]);
                ulonglong2 b = pr[j2];
                accR[2 * j2]     = ffma2(b.x, hd, accR[2 * j2]);
                accR[2 * j2 + 1] = ffma2(b.y, hd, accR[2 * j2 + 1]);
            }
        }
        // r gate: + W_ih_r x, sigmoid
#pragma unroll
        for (int f = 0; f < 6; f++) {
            u64 xd = pk2(xv[f], xv[f]);
#pragma unroll
            for (int jp = 0; jp < 8; jp++)
                accR[jp] = ffma2(sm.uir[f * 16 + jb + jp], xd, accR[jp]);
        }
#pragma unroll
        for (int jp = 0; jp < 8; jp++) {
            float2 a = up2(accR[jp]);
            accR[jp] = pk2(sigm(a.x), sigm(a.y));
        }
        // n = tanh( bin + W_ih_n x + r * accN )
#pragma unroll
        for (int jp = 0; jp < 8; jp++) accN[jp] = ffma2(accR[jp], accN[jp], sm.bin[jb + jp]);
#pragma unroll
        for (int f = 0; f < 6; f++) {
            u64 xd = pk2(xv[f], xv[f]);
#pragma unroll
            for (int jp = 0; jp < 8; jp++)
                accN[jp] = ffma2(sm.uin[f * 16 + jb + jp], xd, accN[jp]);
        }
#pragma unroll
        for (int jp = 0; jp < 8; jp++) {
            float2 v = up2(accN[jp]);
            accN[jp] = pk2(tanh_fast(v.x), tanh_fast(v.y));
        }

        // ---- z pass: accR = bz + Whh_z h + W_ih_z x ----
#pragma unroll
        for (int jp = 0; jp < 8; jp++) accR[jp] = sm.bz[jb + jp];
#pragma unroll 8
        for (int k = 0; k < 32; k++) {
            u64 hd = pk2(hf[k], hf[k]);
            const ulonglong2* pz = reinterpret_cast<const ulonglong2*>(&sm.wz[k * 16 + jb]);
#pragma unroll
            for (int j2 = 0; j2 < 4; j2++) {
                ulonglong2 b = pz[j2];
                accR[2 * j2]     = ffma2(b.x, hd, accR[2 * j2]);
                accR[2 * j2 + 1] = ffma2(b.y, hd, accR[2 * j2 + 1]);
            }
        }
#pragma unroll
        for (int f = 0; f < 6; f++) {
            u64 xd = pk2(xv[f], xv[f]);
#pragma unroll
            for (int jp = 0; jp < 8; jp++)
                accR[jp] = ffma2(sm.uiz[f * 16 + jb + jp], xd, accR[jp]);
        }

        // ---- h' = n + z*(h_old - n) for own 16 outputs ----
#pragma unroll
        for (int jp = 0; jp < 8; jp++) {
            float2 za = up2(accR[jp]);
            float z0 = sigm(za.x), z1 = sigm(za.y);
            float2 nn = up2(accN[jp]);
            float h0 = half ? hf[16 + 2 * jp]     : hf[2 * jp];
            float h1 = half ? hf[16 + 2 * jp + 1] : hf[2 * jp + 1];
            newh[2 * jp]     = nn.x + z0 * (h0 - nn.x);
            newh[2 * jp + 1] = nn.y + z1 * (h1 - nn.y);
        }
        // ---- exchange halves -> rebuild hf[32] ----
#pragma unroll
        for (int i = 0; i < 16; i++) {
            float mine = newh[i];
            float theirs = __shfl_xor_sync(0xffffffffu, mine, 16);
            hf[i]      = half ? theirs : mine;
            hf[16 + i] = half ? mine   : theirs;
        }
#pragma unroll
        for (int f = 0; f < 6; f++) xv[f] = xn[f];
    }

    if (node < NN) {
#pragma unroll
        for (int i = 0; i < 16; i++) {
            float v = newh[i];
            g_A[(size_t)node * 32 + half * 16 + i] = v > 0.f ? v : 0.01f * v;
        }
    }
}

// ---------------- hypergraph kernels ----------------
__device__ __forceinline__ void red_add_v2(float* p, float a, float b) {
    asm volatile("red.global.add.v2.f32 [%0], {%1, %2};"
                 :: "l"(p), "f"(a), "f"(b) : "memory");
}
__global__ void zero_deg_kernel() {
    int i = blockIdx.x * blockDim.x + threadIdx.x;
    if (i < NE) g_degB[i] = 0.f;
    if (i < NN) g_degD[i] = 0.f;
}
__global__ void count_deg_kernel(const int* __restrict__ nidx, const int* __restrict__ eidx) {
    int i = blockIdx.x * blockDim.x + threadIdx.x;
    if (i < NI) {
        atomicAdd(&g_degB[eidx[i]], 1.f);
        atomicAdd(&g_degD[nidx[i]], 1.f);
    }
}
__global__ void invert_deg_kernel() {
    int i = blockIdx.x * blockDim.x + threadIdx.x;
    if (i < NE) { float v = g_degB[i]; g_degB[i] = v > 0.f ? 1.f / v : 0.f; }
    if (i < NN) { float v = g_degD[i]; g_degD[i] = v > 0.f ? 1.f / v : 0.f; }
}
__global__ void zero_ef_agg_kernel() {
    int i = blockIdx.x * blockDim.x + threadIdx.x;
    if (i < NE * HH) g_EF[i] = 0.f;
    if (i < NN * HH) g_AGG[i] = 0.f;
}
__global__ void scatter_edge_kernel(const int* __restrict__ nidx, const int* __restrict__ eidx) {
    int idx = blockIdx.x * blockDim.x + threadIdx.x;
    if (idx < NI * 16) {
        int i = idx >> 4, c = (idx & 15) * 2;
        const float2 v = *reinterpret_cast<const float2*>(&g_XW[(size_t)nidx[i] * HH + c]);
        red_add_v2(&g_EF[eidx[i] * HH + c], v.x, v.y);
    }
}
__global__ void scatter_node_kernel(const int* __restrict__ nidx, const int* __restrict__ eidx) {
    int idx = blockIdx.x * blockDim.x + threadIdx.x;
    if (idx < NI * 16) {
        int i = idx >> 4, c = (idx & 15) * 2;
        int e = eidx[i];
        float s = g_degB[e];
        const float2 v = *reinterpret_cast<const float2*>(&g_EF[e * HH + c]);
        red_add_v2(&g_AGG[(size_t)nidx[i] * HH + c], v.x * s, v.y * s);
    }
}
__global__ void finalize_kernel(const float* __restrict__ bias) {
    int idx = blockIdx.x * blockDim.x + threadIdx.x;
    if (idx < NN * HH) {
        int n = idx >> 5, c = idx & 31;
        float v = g_AGG[idx] * g_degD[n] + bias[c];
        g_A[idx] = v > 0.f ? v : 0.2f * v;
    }
}
__global__ void dense_kernel(const float* __restrict__ W, const float* __restrict__ bias,
                             float* __restrict__ extout,
                             int nout, int hasBias, int hasAct, float slope) {
    __shared__ float sW[32 * 32];
    for (int i = threadIdx.x; i < nout * 32; i += blockDim.x) sW[i] = W[i];
    __syncthreads();
    int n = blockIdx.x * blockDim.x + threadIdx.x;
    if (n >= NN) return;
    float xin[32];
#pragma unroll
    for (int k = 0; k < 32; k++) xin[k] = g_A[(size_t)n * 32 + k];
    float* o = extout ? extout : g_XW;
    for (int j = 0; j < nout; j++) {
        float acc = hasBias ? bias[j] : 0.f;
#pragma unroll
        for (int k = 0; k < 32; k++) acc = fmaf(xin[k], sW[j * 32 + k], acc);
        if (hasAct) acc = acc > 0.f ? acc : slope * acc;
        o[(size_t)n * nout + j] = acc;
    }
}

// ---------------- launch ----------------
extern "C" void kernel_launch(void* const* d_in, const int* in_sizes, int n_in,
                              void* d_out, int out_size) {
    const float* price = (const float*)d_in[0];
    const float* W_ih = (const float*)d_in[2];
    const float* W_hh = (const float*)d_in[3];
    const float* b_ih = (const float*)d_in[4];
    const float* b_hh = (const float*)d_in[5];
    const float* W1   = (const float*)d_in[6];
    const float* b1   = (const float*)d_in[7];
    const float* W2   = (const float*)d_in[8];
    const float* b2   = (const float*)d_in[9];
    const float* Wl   = (const float*)d_in[10];
    const float* bl   = (const float*)d_in[11];
    const int*   nidx = (const int*)d_in[12];
    const int*   eidx = (const int*)d_in[13];
    float* out = (float*)d_out;

    const int B256 = 256;
    zero_deg_kernel<<<(NN + B256 - 1) / B256, B256>>>();
    count_deg_kernel<<<(NI + B256 - 1) / B256, B256>>>(nidx, eidx);
    invert_deg_kernel<<<(NN + B256 - 1) / B256, B256>>>();

    transpose_kernel<<<dim3((NN + 63) / 64, TT / 16), 256>>>(price);
    gru_kernel<<<(NN + 63) / 64, 128>>>(W_ih, W_hh, b_ih, b_hh);

    // conv1
    dense_kernel<<<(NN + 127) / 128, 128>>>(W1, nullptr, nullptr, 32, 0, 0, 0.f);
    zero_ef_agg_kernel<<<(NN * HH + B256 - 1) / B256, B256>>>();
    scatter_edge_kernel<<<(NI * 16 + B256 - 1) / B256, B256>>>(nidx, eidx);
    scatter_node_kernel<<<(NI * 16 + B256 - 1) / B256, B256>>>(nidx, eidx);
    finalize_kernel<<<(NN * HH + B256 - 1) / B256, B256>>>(b1);

    // conv2
    dense_kernel<<<(NN + 127) / 128, 128>>>(W2, nullptr, nullptr, 32, 0, 0, 0.f);
    zero_ef_agg_kernel<<<(NN * HH + B256 - 1) / B256, B256>>>();
    scatter_edge_kernel<<<(NI * 16 + B256 - 1) / B256, B256>>>(nidx, eidx);
    scatter_node_kernel<<<(NI * 16 + B256 - 1) / B256, B256>>>(nidx, eidx);
    finalize_kernel<<<(NN * HH + B256 - 1) / B256, B256>>>(b2);

    dense_kernel<<<(NN + 127) / 128, 128>>>(Wl, bl, out, RRF, 1, 1, 0.01f);
}

// round 6
// speedup vs baseline: 1.0734x; 1.0734x over previous
#include <cuda_runtime.h>
#include <cstdint>

#define NN   50000
#define TT   128
#define INF  6
#define HH   32
#define NE   2000
#define NI   150000
#define RRF  16

typedef unsigned long long u64;

// ---------------- scratch (device globals, no allocation) ----------------
__device__ float g_A  [NN * HH];
__device__ float g_XW [NN * HH];
__device__ float g_AGG[NN * HH];
__device__ float g_EF [NE * HH];
__device__ float g_degB[NE];
__device__ float g_degD[NN];
__device__ float g_XT [(size_t)TT * INF * NN];  // [t][f][node]

// ---------------- helpers ----------------
__device__ __forceinline__ u64 ffma2(u64 a, u64 b, u64 c) {
    u64 d;
    asm("fma.rn.f32x2 %0, %1, %2, %3;" : "=l"(d) : "l"(a), "l"(b), "l"(c));
    return d;
}
__device__ __forceinline__ u64 pk2(float lo, float hi) {
    u64 r;
    asm("mov.b64 %0, {%1, %2};" : "=l"(r) : "f"(lo), "f"(hi));
    return r;
}
__device__ __forceinline__ float2 up2(u64 v) {
    float2 f;
    asm("mov.b64 {%0, %1}, %2;" : "=f"(f.x), "=f"(f.y) : "l"(v));
    return f;
}
__device__ __forceinline__ float sigm(float x) {
    return __fdividef(1.f, 1.f + __expf(-x));
}
__device__ __forceinline__ float tanh_fast(float x) {
    return __fdividef(2.f, 1.f + __expf(-2.f * x)) - 1.f;
}

// ---------------- transpose price [n][t][f] -> [t][f][n] ----------------
__global__ void __launch_bounds__(256) transpose_kernel(const float* __restrict__ x) {
    __shared__ float s[64 * 97];            // 64 nodes x 96 (t,f) + pad
    const int n0 = blockIdx.x * 64;
    const int t0 = blockIdx.y * 16;         // timestep base of this tile
    for (int i = threadIdx.x; i < 64 * 96; i += 256) {
        int n = i / 96, j = i % 96;
        int nc = n0 + n < NN ? n0 + n : NN - 1;
        s[n * 97 + j] = x[(size_t)nc * (TT * INF) + t0 * INF + j];
    }
    __syncthreads();
    for (int i = threadIdx.x; i < 64 * 96; i += 256) {
        int row = i >> 6, n = i & 63;       // row = t_local*6 + f
        if (n0 + n < NN)
            g_XT[((size_t)t0 * INF + row) * NN + n0 + n] = s[n * 97 + row];
    }
}

// ---------------- GRU kernel ----------------
// 2 threads per node: lane = half*16 + nsub. Each thread computes 16 of the
// 32 outputs (8 f32x2 accumulators); halves exchange h via shfl.xor(16).
// launch_bounds(128,4): 128 regs/thread (NO spills), 16 warps/SM.
struct __align__(16) SmemGRU {
    u64 wn[32 * 16], wr[32 * 16], wz[32 * 16];  // W_hh pairs [k][jp]
    u64 uin[6 * 16], uir[6 * 16], uiz[6 * 16];  // W_ih pairs [f][jp]
    u64 bhn[16], br[16], bz[16], bin[16];
};

__global__ void __launch_bounds__(128, 4) gru_kernel(
    const float* __restrict__ W_ih, const float* __restrict__ W_hh,
    const float* __restrict__ b_ih, const float* __restrict__ b_hh)
{
    __shared__ SmemGRU sm;
    const int tid = threadIdx.x;

    for (int idx = tid; idx < 512; idx += 128) {
        int k = idx >> 4, jp = idx & 15;
        sm.wn[idx] = pk2(W_hh[(64 + 2 * jp) * HH + k], W_hh[(64 + 2 * jp + 1) * HH + k]);
        sm.wr[idx] = pk2(W_hh[(     2 * jp) * HH + k], W_hh[(     2 * jp + 1) * HH + k]);
        sm.wz[idx] = pk2(W_hh[(32 + 2 * jp) * HH + k], W_hh[(32 + 2 * jp + 1) * HH + k]);
    }
    for (int idx = tid; idx < 96; idx += 128) {
        int f = idx >> 4, jp = idx & 15;
        sm.uin[idx] = pk2(W_ih[(64 + 2 * jp) * INF + f], W_ih[(64 + 2 * jp + 1) * INF + f]);
        sm.uir[idx] = pk2(W_ih[(     2 * jp) * INF + f], W_ih[(     2 * jp + 1) * INF + f]);
        sm.uiz[idx] = pk2(W_ih[(32 + 2 * jp) * INF + f], W_ih[(32 + 2 * jp + 1) * INF + f]);
    }
    if (tid < 16) {
        int jp = tid;
        sm.br [jp] = pk2(b_ih[2 * jp] + b_hh[2 * jp],
                         b_ih[2 * jp + 1] + b_hh[2 * jp + 1]);
        sm.bz [jp] = pk2(b_ih[32 + 2 * jp] + b_hh[32 + 2 * jp],
                         b_ih[32 + 2 * jp + 1] + b_hh[32 + 2 * jp + 1]);
        sm.bhn[jp] = pk2(b_hh[64 + 2 * jp], b_hh[64 + 2 * jp + 1]);
        sm.bin[jp] = pk2(b_ih[64 + 2 * jp], b_ih[64 + 2 * jp + 1]);
    }
    __syncthreads();

    const int lane = tid & 31;
    const int warp = tid >> 5;
    const int half = lane >> 4;      // 0: outputs 0..15, 1: outputs 16..31
    const int nsub = lane & 15;
    const int node = blockIdx.x * 64 + warp * 16 + nsub;
    const int nc = node < NN ? node : NN - 1;
    const int jb = half * 8;         // pair offset into [16] rows

    float hf[32];                    // full h (both halves), for k-loop
#pragma unroll
    for (int i = 0; i < 32; i++) hf[i] = 0.f;

    float xv[6], xn[6];
#pragma unroll
    for (int f = 0; f < 6; f++) xv[f] = g_XT[(size_t)f * NN + nc];

    u64 accN[8], accR[8];
    float newh[16];

    for (int t = 0; t < TT; t++) {
        if (t < TT - 1) {
#pragma unroll
            for (int f = 0; f < 6; f++)
                xn[f] = g_XT[((size_t)(t + 1) * INF + f) * NN + nc];
        }

        // ---- merged pass: accN = bhn + Whh_n h ; accR = br + Whh_r h ----
#pragma unroll
        for (int jp = 0; jp < 8; jp++) {
            accN[jp] = sm.bhn[jb + jp];
            accR[jp] = sm.br [jb + jp];
        }
#pragma unroll 8
        for (int k = 0; k < 32; k++) {
            u64 hd = pk2(hf[k], hf[k]);
            const ulonglong2* pn = reinterpret_cast<const ulonglong2*>(&sm.wn[k * 16 + jb]);
            const ulonglong2* pr = reinterpret_cast<const ulonglong2*>(&sm.wr[k * 16 + jb]);
#pragma unroll
            for (int j2 = 0; j2 < 4; j2++) {
                ulonglong2 a = pn[j2];
                accN[2 * j2]     = ffma2(a.x, hd, accN[2 * j2]);
                accN[2 * j2 + 1] = ffma2(a.y, hd, accN[2 * j2 + 1]);
                ulonglong2 b = pr[j2];
                accR[2 * j2]     = ffma2(b.x, hd, accR[2 * j2]);
                accR[2 * j2 + 1] = ffma2(b.y, hd, accR[2 * j2 + 1]);
            }
        }
        // r gate: + W_ih_r x, sigmoid
#pragma unroll
        for (int f = 0; f < 6; f++) {
            u64 xd = pk2(xv[f], xv[f]);
#pragma unroll
            for (int jp = 0; jp < 8; jp++)
                accR[jp] = ffma2(sm.uir[f * 16 + jb + jp], xd, accR[jp]);
        }
#pragma unroll
        for (int jp = 0; jp < 8; jp++) {
            float2 a = up2(accR[jp]);
            accR[jp] = pk2(sigm(a.x), sigm(a.y));
        }
        // n = tanh( bin + W_ih_n x + r * accN )
#pragma unroll
        for (int jp = 0; jp < 8; jp++) accN[jp] = ffma2(accR[jp], accN[jp], sm.bin[jb + jp]);
#pragma unroll
        for (int f = 0; f < 6; f++) {
            u64 xd = pk2(xv[f], xv[f]);
#pragma unroll
            for (int jp = 0; jp < 8; jp++)
                accN[jp] = ffma2(sm.uin[f * 16 + jb + jp], xd, accN[jp]);
        }
#pragma unroll
        for (int jp = 0; jp < 8; jp++) {
            float2 v = up2(accN[jp]);
            accN[jp] = pk2(tanh_fast(v.x), tanh_fast(v.y));
        }

        // ---- z pass: accR = bz + Whh_z h + W_ih_z x ----
#pragma unroll
        for (int jp = 0; jp < 8; jp++) accR[jp] = sm.bz[jb + jp];
#pragma unroll 8
        for (int k = 0; k < 32; k++) {
            u64 hd = pk2(hf[k], hf[k]);
            const ulonglong2* pz = reinterpret_cast<const ulonglong2*>(&sm.wz[k * 16 + jb]);
#pragma unroll
            for (int j2 = 0; j2 < 4; j2++) {
                ulonglong2 b = pz[j2];
                accR[2 * j2]     = ffma2(b.x, hd, accR[2 * j2]);
                accR[2 * j2 + 1] = ffma2(b.y, hd, accR[2 * j2 + 1]);
            }
        }
#pragma unroll
        for (int f = 0; f < 6; f++) {
            u64 xd = pk2(xv[f], xv[f]);
#pragma unroll
            for (int jp = 0; jp < 8; jp++)
                accR[jp] = ffma2(sm.uiz[f * 16 + jb + jp], xd, accR[jp]);
        }

        // ---- h' = n + z*(h_old - n) for own 16 outputs ----
#pragma unroll
        for (int jp = 0; jp < 8; jp++) {
            float2 za = up2(accR[jp]);
            float z0 = sigm(za.x), z1 = sigm(za.y);
            float2 nn = up2(accN[jp]);
            float h0 = half ? hf[16 + 2 * jp]     : hf[2 * jp];
            float h1 = half ? hf[16 + 2 * jp + 1] : hf[2 * jp + 1];
            newh[2 * jp]     = nn.x + z0 * (h0 - nn.x);
            newh[2 * jp + 1] = nn.y + z1 * (h1 - nn.y);
        }
        // ---- exchange halves -> rebuild hf[32] ----
#pragma unroll
        for (int i = 0; i < 16; i++) {
            float mine = newh[i];
            float theirs = __shfl_xor_sync(0xffffffffu, mine, 16);
            hf[i]      = half ? theirs : mine;
            hf[16 + i] = half ? mine   : theirs;
        }
#pragma unroll
        for (int f = 0; f < 6; f++) xv[f] = xn[f];
    }

    if (node < NN) {
#pragma unroll
        for (int i = 0; i < 16; i++) {
            float v = newh[i];
            g_A[(size_t)node * 32 + half * 16 + i] = v > 0.f ? v : 0.01f * v;
        }
    }
}

// ---------------- hypergraph kernels ----------------
__device__ __forceinline__ void red_add_v2(float* p, float a, float b) {
    asm volatile("red.global.add.v2.f32 [%0], {%1, %2};"
                 :: "l"(p), "f"(a), "f"(b) : "memory");
}
__global__ void zero_deg_kernel() {
    int i = blockIdx.x * blockDim.x + threadIdx.x;
    if (i < NE) g_degB[i] = 0.f;
    if (i < NN) g_degD[i] = 0.f;
}
__global__ void count_deg_kernel(const int* __restrict__ nidx, const int* __restrict__ eidx) {
    int i = blockIdx.x * blockDim.x + threadIdx.x;
    if (i < NI) {
        atomicAdd(&g_degB[eidx[i]], 1.f);
        atomicAdd(&g_degD[nidx[i]], 1.f);
    }
}
__global__ void invert_deg_kernel() {
    int i = blockIdx.x * blockDim.x + threadIdx.x;
    if (i < NE) { float v = g_degB[i]; g_degB[i] = v > 0.f ? 1.f / v : 0.f; }
    if (i < NN) { float v = g_degD[i]; g_degD[i] = v > 0.f ? 1.f / v : 0.f; }
}
__global__ void zero_ef_agg_kernel() {
    int i = blockIdx.x * blockDim.x + threadIdx.x;
    if (i < NE * HH) g_EF[i] = 0.f;
    if (i < NN * HH) g_AGG[i] = 0.f;
}
__global__ void scatter_edge_kernel(const int* __restrict__ nidx, const int* __restrict__ eidx) {
    int idx = blockIdx.x * blockDim.x + threadIdx.x;
    if (idx < NI * 16) {
        int i = idx >> 4, c = (idx & 15) * 2;
        const float2 v = *reinterpret_cast<const float2*>(&g_XW[(size_t)nidx[i] * HH + c]);
        red_add_v2(&g_EF[eidx[i] * HH + c], v.x, v.y);
    }
}
__global__ void scatter_node_kernel(const int* __restrict__ nidx, const int* __restrict__ eidx) {
    int idx = blockIdx.x * blockDim.x + threadIdx.x;
    if (idx < NI * 16) {
        int i = idx >> 4, c = (idx & 15) * 2;
        int e = eidx[i];
        float s = g_degB[e];
        const float2 v = *reinterpret_cast<const float2*>(&g_EF[e * HH + c]);
        red_add_v2(&g_AGG[(size_t)nidx[i] * HH + c], v.x * s, v.y * s);
    }
}
__global__ void finalize_kernel(const float* __restrict__ bias) {
    int idx = blockIdx.x * blockDim.x + threadIdx.x;
    if (idx < NN * HH) {
        int n = idx >> 5, c = idx & 31;
        float v = g_AGG[idx] * g_degD[n] + bias[c];
        g_A[idx] = v > 0.f ? v : 0.2f * v;
    }
}
__global__ void dense_kernel(const float* __restrict__ W, const float* __restrict__ bias,
                             float* __restrict__ extout,
                             int nout, int hasBias, int hasAct, float slope) {
    __shared__ float sW[32 * 32];
    for (int i = threadIdx.x; i < nout * 32; i += blockDim.x) sW[i] = W[i];
    __syncthreads();
    int n = blockIdx.x * blockDim.x + threadIdx.x;
    if (n >= NN) return;
    float xin[32];
#pragma unroll
    for (int k = 0; k < 32; k++) xin[k] = g_A[(size_t)n * 32 + k];
    float* o = extout ? extout : g_XW;
    for (int j = 0; j < nout; j++) {
        float acc = hasBias ? bias[j] : 0.f;
#pragma unroll
        for (int k = 0; k < 32; k++) acc = fmaf(xin[k], sW[j * 32 + k], acc);
        if (hasAct) acc = acc > 0.f ? acc : slope * acc;
        o[(size_t)n * nout + j] = acc;
    }
}

// ---------------- launch ----------------
extern "C" void kernel_launch(void* const* d_in, const int* in_sizes, int n_in,
                              void* d_out, int out_size) {
    const float* price = (const float*)d_in[0];
    const float* W_ih = (const float*)d_in[2];
    const float* W_hh = (const float*)d_in[3];
    const float* b_ih = (const float*)d_in[4];
    const float* b_hh = (const float*)d_in[5];
    const float* W1   = (const float*)d_in[6];
    const float* b1   = (const float*)d_in[7];
    const float* W2   = (const float*)d_in[8];
    const float* b2   = (const float*)d_in[9];
    const float* Wl   = (const float*)d_in[10];
    const float* bl   = (const float*)d_in[11];
    const int*   nidx = (const int*)d_in[12];
    const int*   eidx = (const int*)d_in[13];
    float* out = (float*)d_out;

    const int B256 = 256;
    zero_deg_kernel<<<(NN + B256 - 1) / B256, B256>>>();
    count_deg_kernel<<<(NI + B256 - 1) / B256, B256>>>(nidx, eidx);
    invert_deg_kernel<<<(NN + B256 - 1) / B256, B256>>>();

    transpose_kernel<<<dim3((NN + 63) / 64, TT / 16), 256>>>(price);
    gru_kernel<<<(NN + 63) / 64, 128>>>(W_ih, W_hh, b_ih, b_hh);

    // conv1
    dense_kernel<<<(NN + 127) / 128, 128>>>(W1, nullptr, nullptr, 32, 0, 0, 0.f);
    zero_ef_agg_kernel<<<(NN * HH + B256 - 1) / B256, B256>>>();
    scatter_edge_kernel<<<(NI * 16 + B256 - 1) / B256, B256>>>(nidx, eidx);
    scatter_node_kernel<<<(NI * 16 + B256 - 1) / B256, B256>>>(nidx, eidx);
    finalize_kernel<<<(NN * HH + B256 - 1) / B256, B256>>>(b1);

    // conv2
    dense_kernel<<<(NN + 127) / 128, 128>>>(W2, nullptr, nullptr, 32, 0, 0, 0.f);
    zero_ef_agg_kernel<<<(NN * HH + B256 - 1) / B256, B256>>>();
    scatter_edge_kernel<<<(NI * 16 + B256 - 1) / B256, B256>>>(nidx, eidx);
    scatter_node_kernel<<<(NI * 16 + B256 - 1) / B256, B256>>>(nidx, eidx);
    finalize_kernel<<<(NN * HH + B256 - 1) / B256, B256>>>(b2);

    dense_kernel<<<(NN + 127) / 128, 128>>>(Wl, bl, out, RRF, 1, 1, 0.01f);
}

// round 8
// speedup vs baseline: 1.4005x; 1.3048x over previous
#include <cuda_runtime.h>
#include <cstdint>

#define NN   50000
#define TT   128
#define INF  6
#define HH   32
#define NE   2000
#define NI   150000
#define RRF  16

typedef unsigned long long u64;

// ---------------- scratch (device globals, no allocation) ----------------
__device__ float g_A  [NN * HH];
__device__ float g_XW [NN * HH];
__device__ float g_AGG[NN * HH];
__device__ float g_EF [NE * HH];
__device__ float g_degB[NE];
__device__ float g_degD[NN];
__device__ float g_XT [(size_t)TT * INF * NN];  // [t][f][node]

// ---------------- helpers ----------------
__device__ __forceinline__ u64 ffma2(u64 a, u64 b, u64 c) {
    u64 d;
    asm("fma.rn.f32x2 %0, %1, %2, %3;" : "=l"(d) : "l"(a), "l"(b), "l"(c));
    return d;
}
__device__ __forceinline__ u64 pk2(float lo, float hi) {
    u64 r;
    asm("mov.b64 %0, {%1, %2};" : "=l"(r) : "f"(lo), "f"(hi));
    return r;
}
__device__ __forceinline__ float2 up2(u64 v) {
    float2 f;
    asm("mov.b64 {%0, %1}, %2;" : "=f"(f.x), "=f"(f.y) : "l"(v));
    return f;
}
__device__ __forceinline__ float sigm(float x) {
    return __fdividef(1.f, 1.f + __expf(-x));
}
__device__ __forceinline__ float tanh_fast(float x) {
    return __fdividef(2.f, 1.f + __expf(-2.f * x)) - 1.f;
}

// ---------------- transpose price [n][t][f] -> [t][f][n] ----------------
__global__ void __launch_bounds__(256) transpose_kernel(const float* __restrict__ x) {
    __shared__ float s[64 * 97];
    const int n0 = blockIdx.x * 64;
    const int t0 = blockIdx.y * 16;
    for (int i = threadIdx.x; i < 64 * 96; i += 256) {
        int n = i / 96, j = i % 96;
        int nc = n0 + n < NN ? n0 + n : NN - 1;
        s[n * 97 + j] = x[(size_t)nc * (TT * INF) + t0 * INF + j];
    }
    __syncthreads();
    for (int i = threadIdx.x; i < 64 * 96; i += 256) {
        int row = i >> 6, n = i & 63;
        if (n0 + n < NN)
            g_XT[((size_t)t0 * INF + row) * NN + n0 + n] = s[n * 97 + row];
    }
}

// ---------------- GRU kernel ----------------
// One thread = one node. h[32] in registers; weights packed as f32x2 pairs in
// shared (uniform broadcast LDS). launch_bounds(64,5): reg cap 204 — gives
// ptxas headroom to software-pipeline the LDS->FFMA2 weight stream.
struct __align__(16) SmemGRU {
    u64 wr[32 * 16], wz[32 * 16], wn[32 * 16];  // W_hh pairs [k][jp]
    u64 uir[6 * 16], uiz[6 * 16], uin[6 * 16];  // W_ih pairs [f][jp]
    u64 br[16], bz[16], bhn[16], bin[16];
};

__global__ void __launch_bounds__(64, 5) gru_kernel(
    const float* __restrict__ W_ih, const float* __restrict__ W_hh,
    const float* __restrict__ b_ih, const float* __restrict__ b_hh)
{
    __shared__ SmemGRU sm;
    const int tid = threadIdx.x;

    for (int idx = tid; idx < 512; idx += 64) {
        int k = idx >> 4, jp = idx & 15;
        sm.wr[idx] = pk2(W_hh[(     2 * jp) * HH + k], W_hh[(     2 * jp + 1) * HH + k]);
        sm.wz[idx] = pk2(W_hh[(32 + 2 * jp) * HH + k], W_hh[(32 + 2 * jp + 1) * HH + k]);
        sm.wn[idx] = pk2(W_hh[(64 + 2 * jp) * HH + k], W_hh[(64 + 2 * jp + 1) * HH + k]);
    }
    for (int idx = tid; idx < 96; idx += 64) {
        int f = idx >> 4, jp = idx & 15;
        sm.uir[idx] = pk2(W_ih[(     2 * jp) * INF + f], W_ih[(     2 * jp + 1) * INF + f]);
        sm.uiz[idx] = pk2(W_ih[(32 + 2 * jp) * INF + f], W_ih[(32 + 2 * jp + 1) * INF + f]);
        sm.uin[idx] = pk2(W_ih[(64 + 2 * jp) * INF + f], W_ih[(64 + 2 * jp + 1) * INF + f]);
    }
    if (tid < 16) {
        int jp = tid;
        sm.br [jp] = pk2(b_ih[2 * jp] + b_hh[2 * jp],
                         b_ih[2 * jp + 1] + b_hh[2 * jp + 1]);
        sm.bz [jp] = pk2(b_ih[32 + 2 * jp] + b_hh[32 + 2 * jp],
                         b_ih[32 + 2 * jp + 1] + b_hh[32 + 2 * jp + 1]);
        sm.bhn[jp] = pk2(b_hh[64 + 2 * jp], b_hh[64 + 2 * jp + 1]);
        sm.bin[jp] = pk2(b_ih[64 + 2 * jp], b_ih[64 + 2 * jp + 1]);
    }
    __syncthreads();

    const int node = blockIdx.x * 64 + tid;
    const int nc = node < NN ? node : NN - 1;

    float h[32];
#pragma unroll
    for (int i = 0; i < 32; i++) h[i] = 0.f;

    float xv[6], xn[6];
#pragma unroll
    for (int f = 0; f < 6; f++) xv[f] = g_XT[(size_t)f * NN + nc];

    u64 accR[16], accZ[16], accN[16];

    for (int t = 0; t < TT; t++) {
        if (t < TT - 1) {
#pragma unroll
            for (int f = 0; f < 6; f++)
                xn[f] = g_XT[((size_t)(t + 1) * INF + f) * NN + nc];
        }

        // ---- merged pass: accR = br + Whh_r h ; accZ = bz + Whh_z h ----
#pragma unroll
        for (int jp = 0; jp < 16; jp++) { accR[jp] = sm.br[jp]; accZ[jp] = sm.bz[jp]; }
#pragma unroll 8
        for (int k = 0; k < 32; k++) {
            u64 hd = pk2(h[k], h[k]);
            const ulonglong2* pr = reinterpret_cast<const ulonglong2*>(&sm.wr[k * 16]);
            const ulonglong2* pz = reinterpret_cast<const ulonglong2*>(&sm.wz[k * 16]);
#pragma unroll
            for (int j2 = 0; j2 < 8; j2++) {
                ulonglong2 a = pr[j2];
                accR[2 * j2]     = ffma2(a.x, hd, accR[2 * j2]);
                accR[2 * j2 + 1] = ffma2(a.y, hd, accR[2 * j2 + 1]);
                ulonglong2 b = pz[j2];
                accZ[2 * j2]     = ffma2(b.x, hd, accZ[2 * j2]);
                accZ[2 * j2 + 1] = ffma2(b.y, hd, accZ[2 * j2 + 1]);
            }
        }
#pragma unroll
        for (int f = 0; f < 6; f++) {
            u64 xd = pk2(xv[f], xv[f]);
#pragma unroll
            for (int jp = 0; jp < 16; jp++) {
                accR[jp] = ffma2(sm.uir[f * 16 + jp], xd, accR[jp]);
                accZ[jp] = ffma2(sm.uiz[f * 16 + jp], xd, accZ[jp]);
            }
        }
        // r = sigmoid(accR) (packed, reuse accR); z stays raw until update
#pragma unroll
        for (int jp = 0; jp < 16; jp++) {
            float2 a = up2(accR[jp]);
            accR[jp] = pk2(sigm(a.x), sigm(a.y));
        }

        // ---- n pass: accN = bhn + Whh_n h ----
#pragma unroll
        for (int jp = 0; jp < 16; jp++) accN[jp] = sm.bhn[jp];
#pragma unroll 8
        for (int k = 0; k < 32; k++) {
            u64 hd = pk2(h[k], h[k]);
            const ulonglong2* pn = reinterpret_cast<const ulonglong2*>(&sm.wn[k * 16]);
#pragma unroll
            for (int j2 = 0; j2 < 8; j2++) {
                ulonglong2 a = pn[j2];
                accN[2 * j2]     = ffma2(a.x, hd, accN[2 * j2]);
                accN[2 * j2 + 1] = ffma2(a.y, hd, accN[2 * j2 + 1]);
            }
        }
        // n = tanh( bin + W_ih_n x + r * accN )
#pragma unroll
        for (int jp = 0; jp < 16; jp++) accN[jp] = ffma2(accR[jp], accN[jp], sm.bin[jp]);
#pragma unroll
        for (int f = 0; f < 6; f++) {
            u64 xd = pk2(xv[f], xv[f]);
#pragma unroll
            for (int jp = 0; jp < 16; jp++)
                accN[jp] = ffma2(sm.uin[f * 16 + jp], xd, accN[jp]);
        }

        // ---- h' = n + sigm(z)*(h - n) ----
#pragma unroll
        for (int jp = 0; jp < 16; jp++) {
            float2 za = up2(accZ[jp]);
            float z0 = sigm(za.x), z1 = sigm(za.y);
            float2 v = up2(accN[jp]);
            float n0 = tanh_fast(v.x), n1 = tanh_fast(v.y);
            h[2 * jp]     = n0 + z0 * (h[2 * jp]     - n0);
            h[2 * jp + 1] = n1 + z1 * (h[2 * jp + 1] - n1);
        }
#pragma unroll
        for (int f = 0; f < 6; f++) xv[f] = xn[f];
    }

    if (node < NN) {
#pragma unroll
        for (int c = 0; c < 32; c++) {
            float v = h[c];
            g_A[(size_t)node * 32 + c] = v > 0.f ? v : 0.01f * v;
        }
    }
}

// ---------------- hypergraph kernels ----------------
__device__ __forceinline__ void red_add_v2(float* p, float a, float b) {
    asm volatile("red.global.add.v2.f32 [%0], {%1, %2};"
                 :: "l"(p), "f"(a), "f"(b) : "memory");
}
__global__ void zero_deg_kernel() {
    int i = blockIdx.x * blockDim.x + threadIdx.x;
    if (i < NE) g_degB[i] = 0.f;
    if (i < NN) g_degD[i] = 0.f;
}
__global__ void count_deg_kernel(const int* __restrict__ nidx, const int* __restrict__ eidx) {
    int i = blockIdx.x * blockDim.x + threadIdx.x;
    if (i < NI) {
        atomicAdd(&g_degB[eidx[i]], 1.f);
        atomicAdd(&g_degD[nidx[i]], 1.f);
    }
}
__global__ void invert_deg_kernel() {
    int i = blockIdx.x * blockDim.x + threadIdx.x;
    if (i < NE) { float v = g_degB[i]; g_degB[i] = v > 0.f ? 1.f / v : 0.f; }
    if (i < NN) { float v = g_degD[i]; g_degD[i] = v > 0.f ? 1.f / v : 0.f; }
}
__global__ void zero_ef_agg_kernel() {
    int i = blockIdx.x * blockDim.x + threadIdx.x;
    if (i < NE * HH) g_EF[i] = 0.f;
    if (i < NN * HH) g_AGG[i] = 0.f;
}
__global__ void scatter_edge_kernel(const int* __restrict__ nidx, const int* __restrict__ eidx) {
    int idx = blockIdx.x * blockDim.x + threadIdx.x;
    if (idx < NI * 16) {
        int i = idx >> 4, c = (idx & 15) * 2;
        const float2 v = *reinterpret_cast<const float2*>(&g_XW[(size_t)nidx[i] * HH + c]);
        red_add_v2(&g_EF[eidx[i] * HH + c], v.x, v.y);
    }
}
__global__ void scatter_node_kernel(const int* __restrict__ nidx, const int* __restrict__ eidx) {
    int idx = blockIdx.x * blockDim.x + threadIdx.x;
    if (idx < NI * 16) {
        int i = idx >> 4, c = (idx & 15) * 2;
        int e = eidx[i];
        float s = g_degB[e];
        const float2 v = *reinterpret_cast<const float2*>(&g_EF[e * HH + c]);
        red_add_v2(&g_AGG[(size_t)nidx[i] * HH + c], v.x * s, v.y * s);
    }
}
__global__ void finalize_kernel(const float* __restrict__ bias) {
    int idx = blockIdx.x * blockDim.x + threadIdx.x;
    if (idx < NN * HH) {
        int n = idx >> 5, c = idx & 31;
        float v = g_AGG[idx] * g_degD[n] + bias[c];
        g_A[idx] = v > 0.f ? v : 0.2f * v;
    }
}
__global__ void dense_kernel(const float* __restrict__ W, const float* __restrict__ bias,
                             float* __restrict__ extout,
                             int nout, int hasBias, int hasAct, float slope) {
    __shared__ float sW[32 * 32];
    for (int i = threadIdx.x; i < nout * 32; i += blockDim.x) sW[i] = W[i];
    __syncthreads();
    int n = blockIdx.x * blockDim.x + threadIdx.x;
    if (n >= NN) return;
    float xin[32];
#pragma unroll
    for (int k = 0; k < 32; k++) xin[k] = g_A[(size_t)n * 32 + k];
    float* o = extout ? extout : g_XW;
    for (int j = 0; j < nout; j++) {
        float acc = hasBias ? bias[j] : 0.f;
#pragma unroll
        for (int k = 0; k < 32; k++) acc = fmaf(xin[k], sW[j * 32 + k], acc);
        if (hasAct) acc = acc > 0.f ? acc : slope * acc;
        o[(size_t)n * nout + j] = acc;
    }
}

// ---------------- launch ----------------
extern "C" void kernel_launch(void* const* d_in, const int* in_sizes, int n_in,
                              void* d_out, int out_size) {
    const float* price = (const float*)d_in[0];
    const float* W_ih = (const float*)d_in[2];
    const float* W_hh = (const float*)d_in[3];
    const float* b_ih = (const float*)d_in[4];
    const float* b_hh = (const float*)d_in[5];
    const float* W1   = (const float*)d_in[6];
    const float* b1   = (const float*)d_in[7];
    const float* W2   = (const float*)d_in[8];
    const float* b2   = (const float*)d_in[9];
    const float* Wl   = (const float*)d_in[10];
    const float* bl   = (const float*)d_in[11];
    const int*   nidx = (const int*)d_in[12];
    const int*   eidx = (const int*)d_in[13];
    float* out = (float*)d_out;

    const int B256 = 256;
    zero_deg_kernel<<<(NN + B256 - 1) / B256, B256>>>();
    count_deg_kernel<<<(NI + B256 - 1) / B256, B256>>>(nidx, eidx);
    invert_deg_kernel<<<(NN + B256 - 1) / B256, B256>>>();

    transpose_kernel<<<dim3((NN + 63) / 64, TT / 16), 256>>>(price);
    gru_kernel<<<(NN + 63) / 64, 64>>>(W_ih, W_hh, b_ih, b_hh);

    // conv1
    dense_kernel<<<(NN + 127) / 128, 128>>>(W1, nullptr, nullptr, 32, 0, 0, 0.f);
    zero_ef_agg_kernel<<<(NN * HH + B256 - 1) / B256, B256>>>();
    scatter_edge_kernel<<<(NI * 16 + B256 - 1) / B256, B256>>>(nidx, eidx);
    scatter_node_kernel<<<(NI * 16 + B256 - 1) / B256, B256>>>(nidx, eidx);
    finalize_kernel<<<(NN * HH + B256 - 1) / B256, B256>>>(b1);

    // conv2
    dense_kernel<<<(NN + 127) / 128, 128>>>(W2, nullptr, nullptr, 32, 0, 0, 0.f);
    zero_ef_agg_kernel<<<(NN * HH + B256 - 1) / B256, B256>>>();
    scatter_edge_kernel<<<(NI * 16 + B256 - 1) / B256, B256>>>(nidx, eidx);
    scatter_node_kernel<<<(NI * 16 + B256 - 1) / B256, B256>>>(nidx, eidx);
    finalize_kernel<<<(NN * HH + B256 - 1) / B256, B256>>>(b2);

    dense_kernel<<<(NN + 127) / 128, 128>>>(Wl, bl, out, RRF, 1, 1, 0.01f);
}

// round 9
// speedup vs baseline: 1.4132x; 1.0091x over previous
#include <cuda_runtime.h>
#include <cstdint>

#define NN   50000
#define TT   128
#define INF  6
#define HH   32
#define NE   2000
#define NI   150000
#define RRF  16

typedef unsigned long long u64;

// ---------------- scratch (device globals, no allocation) ----------------
__device__ float g_A  [NN * HH];
__device__ float g_XW [NN * HH];
__device__ float g_AGG[NN * HH];
__device__ float g_EF [NE * HH];
__device__ float g_degB[NE];
__device__ float g_degD[NN];
__device__ float g_XT [(size_t)TT * INF * NN];  // [t][f][node]

// ---------------- helpers ----------------
__device__ __forceinline__ u64 ffma2(u64 a, u64 b, u64 c) {
    u64 d;
    asm("fma.rn.f32x2 %0, %1, %2, %3;" : "=l"(d) : "l"(a), "l"(b), "l"(c));
    return d;
}
__device__ __forceinline__ u64 pk2(float lo, float hi) {
    u64 r;
    asm("mov.b64 %0, {%1, %2};" : "=l"(r) : "f"(lo), "f"(hi));
    return r;
}
__device__ __forceinline__ float2 up2(u64 v) {
    float2 f;
    asm("mov.b64 {%0, %1}, %2;" : "=f"(f.x), "=f"(f.y) : "l"(v));
    return f;
}
__device__ __forceinline__ float sigm(float x) {
    return __fdividef(1.f, 1.f + __expf(-x));
}
__device__ __forceinline__ float tanh_fast(float x) {
    return __fdividef(2.f, 1.f + __expf(-2.f * x)) - 1.f;
}

// ---------------- transpose price [n][t][f] -> [t][f][n] ----------------
__global__ void __launch_bounds__(256) transpose_kernel(const float* __restrict__ x) {
    __shared__ float s[64 * 97];
    const int n0 = blockIdx.x * 64;
    const int t0 = blockIdx.y * 16;
    for (int i = threadIdx.x; i < 64 * 96; i += 256) {
        int n = i / 96, j = i % 96;
        int nc = n0 + n < NN ? n0 + n : NN - 1;
        s[n * 97 + j] = x[(size_t)nc * (TT * INF) + t0 * INF + j];
    }
    __syncthreads();
    for (int i = threadIdx.x; i < 64 * 96; i += 256) {
        int row = i >> 6, n = i & 63;
        if (n0 + n < NN)
            g_XT[((size_t)t0 * INF + row) * NN + n0 + n] = s[n * 97 + row];
    }
}

// ---------------- GRU kernel ----------------
// One thread = one node, 32-thread blocks (1 warp).
// launch_bounds(32,11): reg cap 186, 11 blocks/SM -> capacity 1628 >= 1563
// grid blocks = ONE wave (round-8's (64,5) capacity was 740 < 782 -> 2 waves,
// the straggler wave cost ~half the kernel).
struct __align__(16) SmemGRU {
    u64 wr[32 * 16], wz[32 * 16], wn[32 * 16];  // W_hh pairs [k][jp]
    u64 uir[6 * 16], uiz[6 * 16], uin[6 * 16];  // W_ih pairs [f][jp]
    u64 br[16], bz[16], bhn[16], bin[16];
};

__global__ void __launch_bounds__(32, 11) gru_kernel(
    const float* __restrict__ W_ih, const float* __restrict__ W_hh,
    const float* __restrict__ b_ih, const float* __restrict__ b_hh)
{
    __shared__ SmemGRU sm;
    const int tid = threadIdx.x;

    for (int idx = tid; idx < 512; idx += 32) {
        int k = idx >> 4, jp = idx & 15;
        sm.wr[idx] = pk2(W_hh[(     2 * jp) * HH + k], W_hh[(     2 * jp + 1) * HH + k]);
        sm.wz[idx] = pk2(W_hh[(32 + 2 * jp) * HH + k], W_hh[(32 + 2 * jp + 1) * HH + k]);
        sm.wn[idx] = pk2(W_hh[(64 + 2 * jp) * HH + k], W_hh[(64 + 2 * jp + 1) * HH + k]);
    }
    for (int idx = tid; idx < 96; idx += 32) {
        int f = idx >> 4, jp = idx & 15;
        sm.uir[idx] = pk2(W_ih[(     2 * jp) * INF + f], W_ih[(     2 * jp + 1) * INF + f]);
        sm.uiz[idx] = pk2(W_ih[(32 + 2 * jp) * INF + f], W_ih[(32 + 2 * jp + 1) * INF + f]);
        sm.uin[idx] = pk2(W_ih[(64 + 2 * jp) * INF + f], W_ih[(64 + 2 * jp + 1) * INF + f]);
    }
    if (tid < 16) {
        int jp = tid;
        sm.br [jp] = pk2(b_ih[2 * jp] + b_hh[2 * jp],
                         b_ih[2 * jp + 1] + b_hh[2 * jp + 1]);
        sm.bz [jp] = pk2(b_ih[32 + 2 * jp] + b_hh[32 + 2 * jp],
                         b_ih[32 + 2 * jp + 1] + b_hh[32 + 2 * jp + 1]);
        sm.bhn[jp] = pk2(b_hh[64 + 2 * jp], b_hh[64 + 2 * jp + 1]);
        sm.bin[jp] = pk2(b_ih[64 + 2 * jp], b_ih[64 + 2 * jp + 1]);
    }
    __syncthreads();

    const int node = blockIdx.x * 32 + tid;
    const int nc = node < NN ? node : NN - 1;

    float h[32];
#pragma unroll
    for (int i = 0; i < 32; i++) h[i] = 0.f;

    float xv[6], xn[6];
#pragma unroll
    for (int f = 0; f < 6; f++) xv[f] = g_XT[(size_t)f * NN + nc];

    u64 accR[16], accZ[16], accN[16];

    for (int t = 0; t < TT; t++) {
        if (t < TT - 1) {
#pragma unroll
            for (int f = 0; f < 6; f++)
                xn[f] = g_XT[((size_t)(t + 1) * INF + f) * NN + nc];
        }

        // ---- merged pass: accR = br + Whh_r h ; accZ = bz + Whh_z h ----
#pragma unroll
        for (int jp = 0; jp < 16; jp++) { accR[jp] = sm.br[jp]; accZ[jp] = sm.bz[jp]; }
#pragma unroll 8
        for (int k = 0; k < 32; k++) {
            u64 hd = pk2(h[k], h[k]);
            const ulonglong2* pr = reinterpret_cast<const ulonglong2*>(&sm.wr[k * 16]);
            const ulonglong2* pz = reinterpret_cast<const ulonglong2*>(&sm.wz[k * 16]);
#pragma unroll
            for (int j2 = 0; j2 < 8; j2++) {
                ulonglong2 a = pr[j2];
                accR[2 * j2]     = ffma2(a.x, hd, accR[2 * j2]);
                accR[2 * j2 + 1] = ffma2(a.y, hd, accR[2 * j2 + 1]);
                ulonglong2 b = pz[j2];
                accZ[2 * j2]     = ffma2(b.x, hd, accZ[2 * j2]);
                accZ[2 * j2 + 1] = ffma2(b.y, hd, accZ[2 * j2 + 1]);
            }
        }
#pragma unroll
        for (int f = 0; f < 6; f++) {
            u64 xd = pk2(xv[f], xv[f]);
#pragma unroll
            for (int jp = 0; jp < 16; jp++) {
                accR[jp] = ffma2(sm.uir[f * 16 + jp], xd, accR[jp]);
                accZ[jp] = ffma2(sm.uiz[f * 16 + jp], xd, accZ[jp]);
            }
        }
        // r = sigmoid(accR) (packed, reuse accR); z stays raw until update
#pragma unroll
        for (int jp = 0; jp < 16; jp++) {
            float2 a = up2(accR[jp]);
            accR[jp] = pk2(sigm(a.x), sigm(a.y));
        }

        // ---- n pass: accN = bhn + Whh_n h ----
#pragma unroll
        for (int jp = 0; jp < 16; jp++) accN[jp] = sm.bhn[jp];
#pragma unroll 8
        for (int k = 0; k < 32; k++) {
            u64 hd = pk2(h[k], h[k]);
            const ulonglong2* pn = reinterpret_cast<const ulonglong2*>(&sm.wn[k * 16]);
#pragma unroll
            for (int j2 = 0; j2 < 8; j2++) {
                ulonglong2 a = pn[j2];
                accN[2 * j2]     = ffma2(a.x, hd, accN[2 * j2]);
                accN[2 * j2 + 1] = ffma2(a.y, hd, accN[2 * j2 + 1]);
            }
        }
        // n = tanh( bin + W_ih_n x + r * accN )
#pragma unroll
        for (int jp = 0; jp < 16; jp++) accN[jp] = ffma2(accR[jp], accN[jp], sm.bin[jp]);
#pragma unroll
        for (int f = 0; f < 6; f++) {
            u64 xd = pk2(xv[f], xv[f]);
#pragma unroll
            for (int jp = 0; jp < 16; jp++)
                accN[jp] = ffma2(sm.uin[f * 16 + jp], xd, accN[jp]);
        }

        // ---- h' = n + sigm(z)*(h - n) ----
#pragma unroll
        for (int jp = 0; jp < 16; jp++) {
            float2 za = up2(accZ[jp]);
            float z0 = sigm(za.x), z1 = sigm(za.y);
            float2 v = up2(accN[jp]);
            float n0 = tanh_fast(v.x), n1 = tanh_fast(v.y);
            h[2 * jp]     = n0 + z0 * (h[2 * jp]     - n0);
            h[2 * jp + 1] = n1 + z1 * (h[2 * jp + 1] - n1);
        }
#pragma unroll
        for (int f = 0; f < 6; f++) xv[f] = xn[f];
    }

    if (node < NN) {
#pragma unroll
        for (int c = 0; c < 32; c++) {
            float v = h[c];
            g_A[(size_t)node * 32 + c] = v > 0.f ? v : 0.01f * v;
        }
    }
}

// ---------------- hypergraph kernels ----------------
__device__ __forceinline__ void red_add_v2(float* p, float a, float b) {
    asm volatile("red.global.add.v2.f32 [%0], {%1, %2};"
                 :: "l"(p), "f"(a), "f"(b) : "memory");
}
__global__ void zero_deg_kernel() {
    int i = blockIdx.x * blockDim.x + threadIdx.x;
    if (i < NE) g_degB[i] = 0.f;
    if (i < NN) g_degD[i] = 0.f;
}
__global__ void count_deg_kernel(const int* __restrict__ nidx, const int* __restrict__ eidx) {
    int i = blockIdx.x * blockDim.x + threadIdx.x;
    if (i < NI) {
        atomicAdd(&g_degB[eidx[i]], 1.f);
        atomicAdd(&g_degD[nidx[i]], 1.f);
    }
}
__global__ void invert_deg_kernel() {
    int i = blockIdx.x * blockDim.x + threadIdx.x;
    if (i < NE) { float v = g_degB[i]; g_degB[i] = v > 0.f ? 1.f / v : 0.f; }
    if (i < NN) { float v = g_degD[i]; g_degD[i] = v > 0.f ? 1.f / v : 0.f; }
}
__global__ void zero_ef_agg_kernel() {
    int i = blockIdx.x * blockDim.x + threadIdx.x;
    if (i < NE * HH) g_EF[i] = 0.f;
    if (i < NN * HH) g_AGG[i] = 0.f;
}
__global__ void scatter_edge_kernel(const int* __restrict__ nidx, const int* __restrict__ eidx) {
    int idx = blockIdx.x * blockDim.x + threadIdx.x;
    if (idx < NI * 16) {
        int i = idx >> 4, c = (idx & 15) * 2;
        const float2 v = *reinterpret_cast<const float2*>(&g_XW[(size_t)nidx[i] * HH + c]);
        red_add_v2(&g_EF[eidx[i] * HH + c], v.x, v.y);
    }
}
__global__ void scatter_node_kernel(const int* __restrict__ nidx, const int* __restrict__ eidx) {
    int idx = blockIdx.x * blockDim.x + threadIdx.x;
    if (idx < NI * 16) {
        int i = idx >> 4, c = (idx & 15) * 2;
        int e = eidx[i];
        float s = g_degB[e];
        const float2 v = *reinterpret_cast<const float2*>(&g_EF[e * HH + c]);
        red_add_v2(&g_AGG[(size_t)nidx[i] * HH + c], v.x * s, v.y * s);
    }
}
__global__ void finalize_kernel(const float* __restrict__ bias) {
    int idx = blockIdx.x * blockDim.x + threadIdx.x;
    if (idx < NN * HH) {
        int n = idx >> 5, c = idx & 31;
        float v = g_AGG[idx] * g_degD[n] + bias[c];
        g_A[idx] = v > 0.f ? v : 0.2f * v;
    }
}
__global__ void dense_kernel(const float* __restrict__ W, const float* __restrict__ bias,
                             float* __restrict__ extout,
                             int nout, int hasBias, int hasAct, float slope) {
    __shared__ float sW[32 * 32];
    for (int i = threadIdx.x; i < nout * 32; i += blockDim.x) sW[i] = W[i];
    __syncthreads();
    int n = blockIdx.x * blockDim.x + threadIdx.x;
    if (n >= NN) return;
    float xin[32];
#pragma unroll
    for (int k = 0; k < 32; k++) xin[k] = g_A[(size_t)n * 32 + k];
    float* o = extout ? extout : g_XW;
    for (int j = 0; j < nout; j++) {
        float acc = hasBias ? bias[j] : 0.f;
#pragma unroll
        for (int k = 0; k < 32; k++) acc = fmaf(xin[k], sW[j * 32 + k], acc);
        if (hasAct) acc = acc > 0.f ? acc : slope * acc;
        o[(size_t)n * nout + j] = acc;
    }
}

// ---------------- launch ----------------
extern "C" void kernel_launch(void* const* d_in, const int* in_sizes, int n_in,
                              void* d_out, int out_size) {
    const float* price = (const float*)d_in[0];
    const float* W_ih = (const float*)d_in[2];
    const float* W_hh = (const float*)d_in[3];
    const float* b_ih = (const float*)d_in[4];
    const float* b_hh = (const float*)d_in[5];
    const float* W1   = (const float*)d_in[6];
    const float* b1   = (const float*)d_in[7];
    const float* W2   = (const float*)d_in[8];
    const float* b2   = (const float*)d_in[9];
    const float* Wl   = (const float*)d_in[10];
    const float* bl   = (const float*)d_in[11];
    const int*   nidx = (const int*)d_in[12];
    const int*   eidx = (const int*)d_in[13];
    float* out = (float*)d_out;

    const int B256 = 256;
    zero_deg_kernel<<<(NN + B256 - 1) / B256, B256>>>();
    count_deg_kernel<<<(NI + B256 - 1) / B256, B256>>>(nidx, eidx);
    invert_deg_kernel<<<(NN + B256 - 1) / B256, B256>>>();

    transpose_kernel<<<dim3((NN + 63) / 64, TT / 16), 256>>>(price);
    gru_kernel<<<(NN + 31) / 32, 32>>>(W_ih, W_hh, b_ih, b_hh);

    // conv1
    dense_kernel<<<(NN + 127) / 128, 128>>>(W1, nullptr, nullptr, 32, 0, 0, 0.f);
    zero_ef_agg_kernel<<<(NN * HH + B256 - 1) / B256, B256>>>();
    scatter_edge_kernel<<<(NI * 16 + B256 - 1) / B256, B256>>>(nidx, eidx);
    scatter_node_kernel<<<(NI * 16 + B256 - 1) / B256, B256>>>(nidx, eidx);
    finalize_kernel<<<(NN * HH + B256 - 1) / B256, B256>>>(b1);

    // conv2
    dense_kernel<<<(NN + 127) / 128, 128>>>(W2, nullptr, nullptr, 32, 0, 0, 0.f);
    zero_ef_agg_kernel<<<(NN * HH + B256 - 1) / B256, B256>>>();
    scatter_edge_kernel<<<(NI * 16 + B256 - 1) / B256, B256>>>(nidx, eidx);
    scatter_node_kernel<<<(NI * 16 + B256 - 1) / B256, B256>>>(nidx, eidx);
    finalize_kernel<<<(NN * HH + B256 - 1) / B256, B256>>>(b2);

    dense_kernel<<<(NN + 127) / 128, 128>>>(Wl, bl, out, RRF, 1, 1, 0.01f);
}

// round 11
// speedup vs baseline: 1.4797x; 1.0470x over previous
#include <cuda_runtime.h>
#include <cstdint>

#define NN   50000
#define TT   128
#define INF  6
#define HH   32
#define NE   2000
#define NI   150000
#define RRF  16

typedef unsigned long long u64;

// ---------------- scratch (device globals, no allocation) ----------------
__device__ float g_A  [NN * HH];
__device__ float g_XW [NN * HH];
__device__ float g_AGG[NN * HH];
__device__ float g_EF [NE * HH];
__device__ float g_degB[NE];
__device__ float g_degD[NN];
__device__ float g_XT [(size_t)TT * INF * NN];  // [t][f][node]

// ---------------- helpers ----------------
__device__ __forceinline__ u64 ffma2(u64 a, u64 b, u64 c) {
    u64 d;
    asm("fma.rn.f32x2 %0, %1, %2, %3;" : "=l"(d) : "l"(a), "l"(b), "l"(c));
    return d;
}
__device__ __forceinline__ u64 pk2(float lo, float hi) {
    u64 r;
    asm("mov.b64 %0, {%1, %2};" : "=l"(r) : "f"(lo), "f"(hi));
    return r;
}
__device__ __forceinline__ float2 up2(u64 v) {
    float2 f;
    asm("mov.b64 {%0, %1}, %2;" : "=f"(f.x), "=f"(f.y) : "l"(v));
    return f;
}
// single-MUFU activations (sm_75+ tanh.approx: ~1e-5 rel err, 16 cyc)
__device__ __forceinline__ float tanh_fast(float x) {
    float t;
    asm("tanh.approx.f32 %0, %1;" : "=f"(t) : "f"(x));
    return t;
}
__device__ __forceinline__ float sigm(float x) {
    float t;
    asm("tanh.approx.f32 %0, %1;" : "=f"(t) : "f"(0.5f * x));
    return fmaf(t, 0.5f, 0.5f);
}

// ---------------- transpose price [n][t][f] -> [t][f][n] ----------------
__global__ void __launch_bounds__(256) transpose_kernel(const float* __restrict__ x) {
    __shared__ float s[64 * 97];
    const int n0 = blockIdx.x * 64;
    const int t0 = blockIdx.y * 16;
    for (int i = threadIdx.x; i < 64 * 96; i += 256) {
        int n = i / 96, j = i % 96;
        int nc = n0 + n < NN ? n0 + n : NN - 1;
        s[n * 97 + j] = x[(size_t)nc * (TT * INF) + t0 * INF + j];
    }
    __syncthreads();
    for (int i = threadIdx.x; i < 64 * 96; i += 256) {
        int row = i >> 6, n = i & 63;
        if (n0 + n < NN)
            g_XT[((size_t)t0 * INF + row) * NN + n0 + n] = s[n * 97 + row];
    }
}

// ---------------- GRU kernel ----------------
// One thread = one node, 32-thread blocks (1 warp), launch_bounds(32,11):
// reg cap 186, 11 blocks/SM, single wave (1563 blocks <= 148*11).
struct __align__(16) SmemGRU {
    u64 wr[32 * 16], wz[32 * 16], wn[32 * 16];  // W_hh pairs [k][jp]
    u64 uir[6 * 16], uiz[6 * 16], uin[6 * 16];  // W_ih pairs [f][jp]
    u64 br[16], bz[16], bhn[16], bin[16];
};

__global__ void __launch_bounds__(32, 11) gru_kernel(
    const float* __restrict__ W_ih, const float* __restrict__ W_hh,
    const float* __restrict__ b_ih, const float* __restrict__ b_hh)
{
    __shared__ SmemGRU sm;
    const int tid = threadIdx.x;

    for (int idx = tid; idx < 512; idx += 32) {
        int k = idx >> 4, jp = idx & 15;
        sm.wr[idx] = pk2(W_hh[(     2 * jp) * HH + k], W_hh[(     2 * jp + 1) * HH + k]);
        sm.wz[idx] = pk2(W_hh[(32 + 2 * jp) * HH + k], W_hh[(32 + 2 * jp + 1) * HH + k]);
        sm.wn[idx] = pk2(W_hh[(64 + 2 * jp) * HH + k], W_hh[(64 + 2 * jp + 1) * HH + k]);
    }
    for (int idx = tid; idx < 96; idx += 32) {
        int f = idx >> 4, jp = idx & 15;
        sm.uir[idx] = pk2(W_ih[(     2 * jp) * INF + f], W_ih[(     2 * jp + 1) * INF + f]);
        sm.uiz[idx] = pk2(W_ih[(32 + 2 * jp) * INF + f], W_ih[(32 + 2 * jp + 1) * INF + f]);
        sm.uin[idx] = pk2(W_ih[(64 + 2 * jp) * INF + f], W_ih[(64 + 2 * jp + 1) * INF + f]);
    }
    if (tid < 16) {
        int jp = tid;
        sm.br [jp] = pk2(b_ih[2 * jp] + b_hh[2 * jp],
                         b_ih[2 * jp + 1] + b_hh[2 * jp + 1]);
        sm.bz [jp] = pk2(b_ih[32 + 2 * jp] + b_hh[32 + 2 * jp],
                         b_ih[32 + 2 * jp + 1] + b_hh[32 + 2 * jp + 1]);
        sm.bhn[jp] = pk2(b_hh[64 + 2 * jp], b_hh[64 + 2 * jp + 1]);
        sm.bin[jp] = pk2(b_ih[64 + 2 * jp], b_ih[64 + 2 * jp + 1]);
    }
    __syncthreads();

    const int node = blockIdx.x * 32 + tid;
    const int nc = node < NN ? node : NN - 1;

    float h[32];
#pragma unroll
    for (int i = 0; i < 32; i++) h[i] = 0.f;

    float xv[6], xn[6];
#pragma unroll
    for (int f = 0; f < 6; f++) xv[f] = g_XT[(size_t)f * NN + nc];

    u64 accR[16], accZ[16], accN[16];

    for (int t = 0; t < TT; t++) {
        if (t < TT - 1) {
#pragma unroll
            for (int f = 0; f < 6; f++)
                xn[f] = g_XT[((size_t)(t + 1) * INF + f) * NN + nc];
        }

        // ---- merged pass: accR = br + Whh_r h ; accZ = bz + Whh_z h ----
#pragma unroll
        for (int jp = 0; jp < 16; jp++) { accR[jp] = sm.br[jp]; accZ[jp] = sm.bz[jp]; }
#pragma unroll 8
        for (int k = 0; k < 32; k++) {
            u64 hd = pk2(h[k], h[k]);
            const ulonglong2* pr = reinterpret_cast<const ulonglong2*>(&sm.wr[k * 16]);
            const ulonglong2* pz = reinterpret_cast<const ulonglong2*>(&sm.wz[k * 16]);
#pragma unroll
            for (int j2 = 0; j2 < 8; j2++) {
                ulonglong2 a = pr[j2];
                accR[2 * j2]     = ffma2(a.x, hd, accR[2 * j2]);
                accR[2 * j2 + 1] = ffma2(a.y, hd, accR[2 * j2 + 1]);
                ulonglong2 b = pz[j2];
                accZ[2 * j2]     = ffma2(b.x, hd, accZ[2 * j2]);
                accZ[2 * j2 + 1] = ffma2(b.y, hd, accZ[2 * j2 + 1]);
            }
        }
#pragma unroll
        for (int f = 0; f < 6; f++) {
            u64 xd = pk2(xv[f], xv[f]);
#pragma unroll
            for (int jp = 0; jp < 16; jp++) {
                accR[jp] = ffma2(sm.uir[f * 16 + jp], xd, accR[jp]);
                accZ[jp] = ffma2(sm.uiz[f * 16 + jp], xd, accZ[jp]);
            }
        }
        // r = sigmoid(accR) (packed, reuse accR); z stays raw until update
#pragma unroll
        for (int jp = 0; jp < 16; jp++) {
            float2 a = up2(accR[jp]);
            accR[jp] = pk2(sigm(a.x), sigm(a.y));
        }

        // ---- n pass: accN = bhn + Whh_n h ----
#pragma unroll
        for (int jp = 0; jp < 16; jp++) accN[jp] = sm.bhn[jp];
#pragma unroll 8
        for (int k = 0; k < 32; k++) {
            u64 hd = pk2(h[k], h[k]);
            const ulonglong2* pn = reinterpret_cast<const ulonglong2*>(&sm.wn[k * 16]);
#pragma unroll
            for (int j2 = 0; j2 < 8; j2++) {
                ulonglong2 a = pn[j2];
                accN[2 * j2]     = ffma2(a.x, hd, accN[2 * j2]);
                accN[2 * j2 + 1] = ffma2(a.y, hd, accN[2 * j2 + 1]);
            }
        }
        // n = tanh( bin + W_ih_n x + r * accN )
#pragma unroll
        for (int jp = 0; jp < 16; jp++) accN[jp] = ffma2(accR[jp], accN[jp], sm.bin[jp]);
#pragma unroll
        for (int f = 0; f < 6; f++) {
            u64 xd = pk2(xv[f], xv[f]);
#pragma unroll
            for (int jp = 0; jp < 16; jp++)
                accN[jp] = ffma2(sm.uin[f * 16 + jp], xd, accN[jp]);
        }

        // ---- h' = n + sigm(z)*(h - n) ----
#pragma unroll
        for (int jp = 0; jp < 16; jp++) {
            float2 za = up2(accZ[jp]);
            float z0 = sigm(za.x), z1 = sigm(za.y);
            float2 v = up2(accN[jp]);
            float n0 = tanh_fast(v.x), n1 = tanh_fast(v.y);
            h[2 * jp]     = n0 + z0 * (h[2 * jp]     - n0);
            h[2 * jp + 1] = n1 + z1 * (h[2 * jp + 1] - n1);
        }
#pragma unroll
        for (int f = 0; f < 6; f++) xv[f] = xn[f];
    }

    if (node < NN) {
#pragma unroll
        for (int c = 0; c < 32; c++) {
            float v = h[c];
            g_A[(size_t)node * 32 + c] = v > 0.f ? v : 0.01f * v;
        }
    }
}

// ---------------- hypergraph kernels ----------------
__device__ __forceinline__ void red_add_v2(float* p, float a, float b) {
    asm volatile("red.global.add.v2.f32 [%0], {%1, %2};"
                 :: "l"(p), "f"(a), "f"(b) : "memory");
}
__global__ void zero_deg_kernel() {
    int i = blockIdx.x * blockDim.x + threadIdx.x;
    if (i < NE) g_degB[i] = 0.f;
    if (i < NN) g_degD[i] = 0.f;
}
__global__ void count_deg_kernel(const int* __restrict__ nidx, const int* __restrict__ eidx) {
    int i = blockIdx.x * blockDim.x + threadIdx.x;
    if (i < NI) {
        atomicAdd(&g_degB[eidx[i]], 1.f);
        atomicAdd(&g_degD[nidx[i]], 1.f);
    }
}
__global__ void invert_deg_kernel() {
    int i = blockIdx.x * blockDim.x + threadIdx.x;
    if (i < NE) { float v = g_degB[i]; g_degB[i] = v > 0.f ? 1.f / v : 0.f; }
    if (i < NN) { float v = g_degD[i]; g_degD[i] = v > 0.f ? 1.f / v : 0.f; }
}
__global__ void zero_ef_agg_kernel() {
    int i = blockIdx.x * blockDim.x + threadIdx.x;
    if (i < NE * HH) g_EF[i] = 0.f;
    if (i < NN * HH) g_AGG[i] = 0.f;
}
__global__ void scatter_edge_kernel(const int* __restrict__ nidx, const int* __restrict__ eidx) {
    int idx = blockIdx.x * blockDim.x + threadIdx.x;
    if (idx < NI * 16) {
        int i = idx >> 4, c = (idx & 15) * 2;
        const float2 v = *reinterpret_cast<const float2*>(&g_XW[(size_t)nidx[i] * HH + c]);
        red_add_v2(&g_EF[eidx[i] * HH + c], v.x, v.y);
    }
}
__global__ void scatter_node_kernel(const int* __restrict__ nidx, const int* __restrict__ eidx) {
    int idx = blockIdx.x * blockDim.x + threadIdx.x;
    if (idx < NI * 16) {
        int i = idx >> 4, c = (idx & 15) * 2;
        int e = eidx[i];
        float s = g_degB[e];
        const float2 v = *reinterpret_cast<const float2*>(&g_EF[e * HH + c]);
        red_add_v2(&g_AGG[(size_t)nidx[i] * HH + c], v.x * s, v.y * s);
    }
}
__global__ void finalize_kernel(const float* __restrict__ bias) {
    int idx = blockIdx.x * blockDim.x + threadIdx.x;
    if (idx < NN * HH) {
        int n = idx >> 5, c = idx & 31;
        float v = g_AGG[idx] * g_degD[n] + bias[c];
        g_A[idx] = v > 0.f ? v : 0.2f * v;
    }
}
__global__ void dense_kernel(const float* __restrict__ W, const float* __restrict__ bias,
                             float* __restrict__ extout,
                             int nout, int hasBias, int hasAct, float slope) {
    __shared__ float sW[32 * 32];
    for (int i = threadIdx.x; i < nout * 32; i += blockDim.x) sW[i] = W[i];
    __syncthreads();
    int n = blockIdx.x * blockDim.x + threadIdx.x;
    if (n >= NN) return;
    float xin[32];
#pragma unroll
    for (int k = 0; k < 32; k++) xin[k] = g_A[(size_t)n * 32 + k];
    float* o = extout ? extout : g_XW;
    for (int j = 0; j < nout; j++) {
        float acc = hasBias ? bias[j] : 0.f;
#pragma unroll
        for (int k = 0; k < 32; k++) acc = fmaf(xin[k], sW[j * 32 + k], acc);
        if (hasAct) acc = acc > 0.f ? acc : slope * acc;
        o[(size_t)n * nout + j] = acc;
    }
}

// ---------------- launch ----------------
// NOTE: order chosen so gru_kernel is the 4th launch — the profiler has
// captured launch #4 every round. Dependencies: gru needs only transpose;
// invert (needs count) runs before conv1's scatters, which need it.
extern "C" void kernel_launch(void* const* d_in, const int* in_sizes, int n_in,
                              void* d_out, int out_size) {
    const float* price = (const float*)d_in[0];
    const float* W_ih = (const float*)d_in[2];
    const float* W_hh = (const float*)d_in[3];
    const float* b_ih = (const float*)d_in[4];
    const float* b_hh = (const float*)d_in[5];
    const float* W1   = (const float*)d_in[6];
    const float* b1   = (const float*)d_in[7];
    const float* W2   = (const float*)d_in[8];
    const float* b2   = (const float*)d_in[9];
    const float* Wl   = (const float*)d_in[10];
    const float* bl   = (const float*)d_in[11];
    const int*   nidx = (const int*)d_in[12];
    const int*   eidx = (const int*)d_in[13];
    float* out = (float*)d_out;

    const int B256 = 256;
    transpose_kernel<<<dim3((NN + 63) / 64, TT / 16), 256>>>(price);      // 1
    zero_deg_kernel<<<(NN + B256 - 1) / B256, B256>>>();                  // 2
    count_deg_kernel<<<(NI + B256 - 1) / B256, B256>>>(nidx, eidx);       // 3
    gru_kernel<<<(NN + 31) / 32, 32>>>(W_ih, W_hh, b_ih, b_hh);           // 4 <- profiled
    invert_deg_kernel<<<(NN + B256 - 1) / B256, B256>>>();                // 5

    // conv1
    dense_kernel<<<(NN + 127) / 128, 128>>>(W1, nullptr, nullptr, 32, 0, 0, 0.f);
    zero_ef_agg_kernel<<<(NN * HH + B256 - 1) / B256, B256>>>();
    scatter_edge_kernel<<<(NI * 16 + B256 - 1) / B256, B256>>>(nidx, eidx);
    scatter_node_kernel<<<(NI * 16 + B256 - 1) / B256, B256>>>(nidx, eidx);
    finalize_kernel<<<(NN * HH + B256 - 1) / B256, B256>>>(b1);

    // conv2
    dense_kernel<<<(NN + 127) / 128, 128>>>(W2, nullptr, nullptr, 32, 0, 0, 0.f);
    zero_ef_agg_kernel<<<(NN * HH + B256 - 1) / B256, B256>>>();
    scatter_edge_kernel<<<(NI * 16 + B256 - 1) / B256, B256>>>(nidx, eidx);
    scatter_node_kernel<<<(NI * 16 + B256 - 1) / B256, B256>>>(nidx, eidx);
    finalize_kernel<<<(NN * HH + B256 - 1) / B256, B256>>>(b2);

    dense_kernel<<<(NN + 127) / 128, 128>>>(Wl, bl, out, RRF, 1, 1, 0.01f);
}